// round 1
// baseline (speedup 1.0000x reference)
#include <cuda_runtime.h>

// Convex_f: out[b,j,k] = (interior && Dy>0) ? 0.5*(y[j-1]+y[j+1]) - param[j]
//                                          : x[j]
// where y = x + param, Dy = 2*y[j] - y[j-1] - y[j+1].
// Shapes: B=256, N=8192, K=16, float32, contiguous (B,N,K).

#ifndef CB
#define CB 256
#endif

constexpr int Bn = 256;
constexpr int Nn = 8192;
constexpr int Kn = 16;
constexpr int KV = Kn / 4;        // float4 lanes per (b,j) row = 4
constexpr int L  = 32;            // j-strip length per thread
constexpr int STRIPS = Nn / L;    // 256
// total threads = Bn * STRIPS * KV = 256*256*4 = 262144

__global__ __launch_bounds__(CB)
void convex_kernel(const float4* __restrict__ x4,
                   const float4* __restrict__ p4,
                   float4* __restrict__ o4)
{
    int tid   = blockIdx.x * CB + threadIdx.x;
    int kv    = tid & (KV - 1);                 // 0..3
    int strip = (tid >> 2) & (STRIPS - 1);      // 0..255
    int b     = tid >> 10;                      // /(KV*STRIPS)

    // base offset in float4 units for (b, j=0, kv)
    int base = b * (Nn * KV) + kv;
    int j0   = strip * L;

    // Prologue: load y[j0-1] (clamped; unused when j0==0) and y[j0]
    int jm = (j0 > 0) ? (j0 - 1) : 0;
    float4 xm = x4[base + jm * KV];
    float4 pm = p4[base + jm * KV];
    float4 ym1 = make_float4(xm.x + pm.x, xm.y + pm.y, xm.z + pm.z, xm.w + pm.w);

    float4 x0 = x4[base + j0 * KV];
    float4 p0 = p4[base + j0 * KV];
    float4 y0 = make_float4(x0.x + p0.x, x0.y + p0.y, x0.z + p0.z, x0.w + p0.w);

    #pragma unroll
    for (int i = 0; i < L; i++) {
        int j  = j0 + i;
        int jn = (j + 1 < Nn) ? (j + 1) : j;    // clamp; value unused at j==N-1
        float4 xn = x4[base + jn * KV];
        float4 pn = p4[base + jn * KV];
        float4 yn = make_float4(xn.x + pn.x, xn.y + pn.y, xn.z + pn.z, xn.w + pn.w);

        bool interior = (j > 0) && (j < Nn - 1);

        float4 out;
        {
            float Dy  = 2.0f * y0.x - ym1.x - yn.x;
            float alt = 0.5f * (ym1.x + yn.x) - p0.x;
            out.x = (interior && Dy > 0.0f) ? alt : x0.x;
        }
        {
            float Dy  = 2.0f * y0.y - ym1.y - yn.y;
            float alt = 0.5f * (ym1.y + yn.y) - p0.y;
            out.y = (interior && Dy > 0.0f) ? alt : x0.y;
        }
        {
            float Dy  = 2.0f * y0.z - ym1.z - yn.z;
            float alt = 0.5f * (ym1.z + yn.z) - p0.z;
            out.z = (interior && Dy > 0.0f) ? alt : x0.z;
        }
        {
            float Dy  = 2.0f * y0.w - ym1.w - yn.w;
            float alt = 0.5f * (ym1.w + yn.w) - p0.w;
            out.w = (interior && Dy > 0.0f) ? alt : x0.w;
        }

        o4[base + j * KV] = out;

        ym1 = y0; y0 = yn; x0 = xn; p0 = pn;
    }
}

extern "C" void kernel_launch(void* const* d_in, const int* in_sizes, int n_in,
                              void* d_out, int out_size)
{
    const float4* x4 = (const float4*)d_in[0];
    const float4* p4 = (const float4*)d_in[1];
    float4* o4 = (float4*)d_out;

    int total_threads = Bn * STRIPS * KV;       // 262144
    int blocks = total_threads / CB;            // 1024
    convex_kernel<<<blocks, CB>>>(x4, p4, o4);
}